// round 12
// baseline (speedup 1.0000x reference)
#include <cuda_runtime.h>

#define NT 512
typedef unsigned long long ull;

// ---- shared-memory layout (float offsets), aggressively aliased ----
// Region A [0, 8240): E1; after fwd2 dead:
//   E3 at 0 (2112) [also median candidate buffer after fwd4], D3 at 2112,
//   A4 at 4192, D4 at 5248; finally R1 (inv2 out) overwrites all of region A.
// Region B [8240, 16448): D1
// Region C [16448, 20608): E2 then R2
// Region D [20608, 24720): D2
// HIST [24720, 24980): dedicated (fused round-0 histogram during fwd1)
#define OFF_E1   0
#define OFF_E3   0
#define OFF_CAND 0
#define OFF_D3   2112
#define OFF_A4   4192
#define OFF_D4   5248
#define OFF_D1   8240
#define OFF_E2   16448
#define OFF_D2   20608
#define OFF_HIST 24720
#define SMEM_FLOATS (24720 + 260)
#define SMEM_BYTES  (SMEM_FLOATS * 4)
#define CAND_CAP 2048

static constexpr float Hc[16] = {
    0.05441584224308161f,  0.3128715909144659f,   0.6756307362980128f,    0.5853546836548691f,
   -0.015829105256023893f,-0.2840155429624281f,   0.00047248457399797254f,0.128747426620186f,
   -0.01736930100202211f, -0.04408825393106472f,  0.013981027917015516f,  0.008746094047015655f,
   -0.00487035299301066f, -0.0003917403729959771f,0.0006754494059985568f,-0.00011747678400228192f };

__host__ __device__ static constexpr ull pk2(float lo, float hi) {
    return (ull)__builtin_bit_cast(unsigned int, lo) |
           ((ull)__builtin_bit_cast(unsigned int, hi) << 32);
}

#define DECL_FWD_COEF \
    const ull CA2[8] = { pk2(Hc[0],Hc[1]),  pk2(Hc[2],Hc[3]),  pk2(Hc[4],Hc[5]),  pk2(Hc[6],Hc[7]), \
                         pk2(Hc[8],Hc[9]),  pk2(Hc[10],Hc[11]),pk2(Hc[12],Hc[13]),pk2(Hc[14],Hc[15]) }; \
    const ull CD2[8] = { pk2(Hc[15],-Hc[14]),pk2(Hc[13],-Hc[12]),pk2(Hc[11],-Hc[10]),pk2(Hc[9],-Hc[8]), \
                         pk2(Hc[7],-Hc[6]),  pk2(Hc[5],-Hc[4]),  pk2(Hc[3],-Hc[2]),  pk2(Hc[1],-Hc[0]) }

#define DECL_INV_COEF \
    const ull CIA[8] = { pk2(Hc[14],Hc[15]), pk2(Hc[12],Hc[13]), pk2(Hc[10],Hc[11]), pk2(Hc[8],Hc[9]), \
                         pk2(Hc[6],Hc[7]),   pk2(Hc[4],Hc[5]),   pk2(Hc[2],Hc[3]),   pk2(Hc[0],Hc[1]) }; \
    const ull CIC[8] = { pk2(Hc[1],-Hc[0]),  pk2(Hc[3],-Hc[2]),  pk2(Hc[5],-Hc[4]),  pk2(Hc[7],-Hc[6]), \
                         pk2(Hc[9],-Hc[8]),  pk2(Hc[11],-Hc[10]),pk2(Hc[13],-Hc[12]),pk2(Hc[15],-Hc[14]) }

__device__ __forceinline__ void ff2(ull& a, ull v, ull c) {
    asm("fma.rn.f32x2 %0, %1, %2, %0;" : "+l"(a) : "l"(v), "l"(c));
}
__device__ __forceinline__ float hadd2(ull v) {
    float lo, hi;
    asm("mov.b64 {%0, %1}, %2;" : "=f"(lo), "=f"(hi) : "l"(v));
    return lo + hi;
}
__device__ __forceinline__ ull pkf(float lo, float hi) {
    ull r; asm("mov.b64 %0, {%1, %2};" : "=l"(r) : "f"(lo), "f"(hi)); return r;
}
__device__ __forceinline__ float2 upk2(ull v) {
    float2 r; asm("mov.b64 {%0, %1}, %2;" : "=f"(r.x), "=f"(r.y) : "l"(v)); return r;
}

__device__ __forceinline__ int symidx(int m) {
    if (m < 14)     return 13 - m;
    if (m > 16397)  return 32781 - m;
    return m - 14;
}

// Border writes fused into the main loop: thread producing output w also writes
// the symmetric-extension mirror copies of the output buffer.
//   low : caout[t] = ca[13-t],  t in [0,13]   -> w<14 writes caout[13-w]
//   high: caout[2Lc+13-w] = ca[w], w in [Lc-16, Lc-1]
__device__ __forceinline__ void store_fwd_pair(float* __restrict__ caout, float* __restrict__ D,
                                               int caoff, int Lc, int w0, int ext_out,
                                               float ca0, float ca1, float cd0, float cd1)
{
    const bool has1 = (w0 + 1 < Lc);
    if (has1) {
        *(float2*)(caout + caoff + w0) = make_float2(ca0, ca1);
        *(float2*)(D + w0)             = make_float2(cd0, cd1);
    } else if (w0 < Lc) {
        caout[caoff + w0] = ca0; D[w0] = cd0;
    }
    if (ext_out) {
        if (w0 < 14) {
            caout[13 - w0] = ca0;
            if (has1 && w0 + 1 < 14) caout[12 - w0] = ca1;
        }
        if (w0 + 16 >= Lc) {
            if (w0 < Lc) caout[2 * Lc + 13 - w0] = ca0;
            if (has1 && w0 + 17 >= Lc) caout[2 * Lc + 12 - w0] = ca1;
        }
    }
}

// Level-1 forward straight from gmem; fused round-0 median histogram; fused borders.
__device__ void fwd1_gmem(const float* __restrict__ xr,
                          float* __restrict__ E1out,
                          float* __restrict__ D1,
                          int* __restrict__ hist, int tid)
{
    DECL_FWD_COEF;
    for (int v = tid; v < 4100; v += NT) {
        ull P[10];                          // P[p] = (e[2p], e[2p+1]), e[j]=E[4v-2+j]
        if (v >= 4 && v <= 4095) {
            const double2* px = (const double2*)(xr + 4 * v - 16);
            #pragma unroll
            for (int q = 0; q < 5; q++) {
                double2 t = px[q];
                P[2*q]   = __double_as_longlong(t.x);
                P[2*q+1] = __double_as_longlong(t.y);
            }
        } else {
            float e[20];
            e[0] = 0.f; e[1] = 0.f;
            #pragma unroll
            for (int j = 2; j < 20; j++) e[j] = xr[symidx(4 * v - 2 + j)];
            #pragma unroll
            for (int p = 0; p < 10; p++) P[p] = pkf(e[2*p], e[2*p+1]);
        }
        ull a0 = 0, d0 = 0, a1 = 0, d1 = 0;
        #pragma unroll
        for (int m = 0; m < 8; m++) {
            ff2(a0, P[m+1], CA2[m]); ff2(d0, P[m+1], CD2[m]);
            ff2(a1, P[m+2], CA2[m]); ff2(d1, P[m+2], CD2[m]);
        }
        float ca0 = hadd2(a0), cd0 = hadd2(d0);
        float ca1 = hadd2(a1), cd1 = hadd2(d1);
        const int w0 = 2 * v;
        store_fwd_pair(E1out, D1, 14, 8199, w0, 1, ca0, ca1, cd0, cd1);
        if (w0 < 8199)     atomicAdd(&hist[__float_as_uint(fabsf(cd0)) >> 24], 1);
        if (w0 + 1 < 8199) atomicAdd(&hist[__float_as_uint(fabsf(cd1)) >> 24], 1);
    }
    __syncthreads();
}

// Forward DWT one level from an ext smem buffer; fused borders; one barrier.
__device__ __forceinline__ void fwd_level(const float* __restrict__ Ein,
                                          float* __restrict__ caout,
                                          float* __restrict__ D,
                                          int L, int ext_out, int tid)
{
    DECL_FWD_COEF;
    const int Lc    = (L + 15) >> 1;
    const int npair = (Lc + 1) >> 1;
    const int caoff = ext_out ? 14 : 0;
    for (int u = tid; u < npair; u += NT) {
        const double2* p = (const double2*)(Ein + 4 * u);
        ull P[10];
        #pragma unroll
        for (int q = 0; q < 5; q++) {
            double2 t = p[q];
            P[2*q]   = __double_as_longlong(t.x);
            P[2*q+1] = __double_as_longlong(t.y);
        }
        ull a0 = 0, d0 = 0, a1 = 0, d1 = 0;
        #pragma unroll
        for (int m = 0; m < 8; m++) {
            ff2(a0, P[m],   CA2[m]); ff2(d0, P[m],   CD2[m]);
            ff2(a1, P[m+1], CA2[m]); ff2(d1, P[m+1], CD2[m]);
        }
        float ca0 = hadd2(a0), cd0 = hadd2(d0);
        float ca1 = hadd2(a1), cd1 = hadd2(d1);
        store_fwd_pair(caout, D, caoff, Lc, 2 * u, ext_out, ca0, ca1, cd0, cd1);
    }
    __syncthreads();
}

__device__ __forceinline__ float softthr(float v, float thr) {
    return copysignf(fmaxf(fabsf(v) - thr, 0.0f), v);
}

// Inverse DWT one level into smem; (re,ro) packed accumulator; fused threshold.
__device__ __forceinline__ void inv_level(const float* __restrict__ ca,
                                          const float* __restrict__ cd,
                                          float* __restrict__ outsh,
                                          int n_out, float thr, int tid)
{
    DECL_INV_COEF;
    const int nu = (n_out + 7) >> 3;
    for (int u = tid; u < nu; u += NT) {
        const float4* pa = (const float4*)(ca + 4 * u);
        const float4* pc = (const float4*)(cd + 4 * u);
        float4 a0 = pa[0], a1 = pa[1], a2 = pa[2];
        float4 c0 = pc[0], c1 = pc[1], c2 = pc[2];
        float A[12] = { a0.x,a0.y,a0.z,a0.w, a1.x,a1.y,a1.z,a1.w, a2.x,a2.y,a2.z,a2.w };
        float C[12] = { c0.x,c0.y,c0.z,c0.w, c1.x,c1.y,c1.z,c1.w, c2.x,c2.y,c2.z,c2.w };
        ull Ad[12], Cd[12];
        #pragma unroll
        for (int m = 0; m < 12; m++) {
            Ad[m] = pkf(A[m], A[m]);
            float t = softthr(C[m], thr);
            Cd[m] = pkf(t, t);
        }
        float r[8];
        #pragma unroll
        for (int j = 0; j < 4; j++) {
            ull acc = 0;
            #pragma unroll
            for (int i = 0; i < 8; i++) { ff2(acc, Ad[j+i], CIA[i]); ff2(acc, Cd[j+i], CIC[i]); }
            float2 t = upk2(acc);
            r[2*j] = t.x; r[2*j+1] = t.y;
        }
        const int base = 8 * u;
        if (base + 8 <= n_out) {
            *(float4*)(outsh + base)     = make_float4(r[0], r[1], r[2], r[3]);
            *(float4*)(outsh + base + 4) = make_float4(r[4], r[5], r[6], r[7]);
        } else {
            #pragma unroll
            for (int j = 0; j < 8; j++)
                if (base + j < n_out) outsh[base + j] = r[j];
        }
    }
    __syncthreads();
}

// Final inverse level: n_out = 16384, writes straight to gmem.
__device__ __forceinline__ void inv_final(const float* __restrict__ ca,
                                          const float* __restrict__ cd,
                                          float* __restrict__ gout, float thr, int tid)
{
    DECL_INV_COEF;
    for (int u = tid; u < 2048; u += NT) {
        const float4* pa = (const float4*)(ca + 4 * u);
        const float4* pc = (const float4*)(cd + 4 * u);
        float4 a0 = pa[0], a1 = pa[1], a2 = pa[2];
        float4 c0 = pc[0], c1 = pc[1], c2 = pc[2];
        float A[12] = { a0.x,a0.y,a0.z,a0.w, a1.x,a1.y,a1.z,a1.w, a2.x,a2.y,a2.z,a2.w };
        float C[12] = { c0.x,c0.y,c0.z,c0.w, c1.x,c1.y,c1.z,c1.w, c2.x,c2.y,c2.z,c2.w };
        ull Ad[12], Cd[12];
        #pragma unroll
        for (int m = 0; m < 12; m++) {
            Ad[m] = pkf(A[m], A[m]);
            float t = softthr(C[m], thr);
            Cd[m] = pkf(t, t);
        }
        float r[8];
        #pragma unroll
        for (int j = 0; j < 4; j++) {
            ull acc = 0;
            #pragma unroll
            for (int i = 0; i < 8; i++) { ff2(acc, Ad[j+i], CIA[i]); ff2(acc, Cd[j+i], CIC[i]); }
            float2 t = upk2(acc);
            r[2*j] = t.x; r[2*j+1] = t.y;
        }
        float4* po = (float4*)(gout + 8 * u);
        po[0] = make_float4(r[0], r[1], r[2], r[3]);
        po[1] = make_float4(r[4], r[5], r[6], r[7]);
    }
}

// Warp-0 scan of a 256-bin histogram: find bin containing rank kk.
// Writes hist[256] = pref | (bin << shift), hist[257] = residual rank.
__device__ __forceinline__ void hist_select(int* __restrict__ hist, unsigned pref,
                                            int kk, int shift, int tid)
{
    if (tid < 32) {
        int s[8]; int tot = 0;
        #pragma unroll
        for (int j = 0; j < 8; j++) { s[j] = hist[tid * 8 + j]; tot += s[j]; }
        int run = tot;
        #pragma unroll
        for (int off = 1; off < 32; off <<= 1) {
            int n = __shfl_up_sync(0xFFFFFFFFu, run, off);
            if (tid >= (unsigned)off) run += n;
        }
        int excl = run - tot;
        if (kk >= excl && kk < excl + tot) {
            int acc = excl;
            #pragma unroll
            for (int j = 0; j < 8; j++) {
                if (acc + s[j] > kk) {
                    hist[256] = (int)(pref | ((unsigned)(tid * 8 + j) << shift));
                    hist[257] = kk - acc;
                    break;
                }
                acc += s[j];
            }
        }
    }
}

__global__ void __launch_bounds__(NT, 2)
wden_kernel(const float* __restrict__ x, float* __restrict__ out, int rows)
{
    extern __shared__ float sm[];
    const int tid = threadIdx.x;
    const int row = blockIdx.x;

    float* E1 = sm + OFF_E1;
    float* E3 = sm + OFF_E3;
    float* D3 = sm + OFF_D3;
    float* A4 = sm + OFF_A4;
    float* D4 = sm + OFF_D4;
    float* D1 = sm + OFF_D1;
    float* E2 = sm + OFF_E2;
    float* D2 = sm + OFF_D2;
    int*   hist = (int*)(sm + OFF_HIST);
    unsigned* cand = (unsigned*)(sm + OFF_CAND);   // free during median phase

    const float* xr = x + (size_t)row * 16384;

    for (int i = tid; i < 260; i += NT) hist[i] = 0;
    __syncthreads();

    // forward DWT: 16384 -> 8199 -> 4107 -> 2061 -> 1038
    fwd1_gmem(xr, E1, D1, hist, tid);           // also fills round-0 histogram
    fwd_level(E1, E2, D2, 8199,  1, tid);
    fwd_level(E2, E3, D3, 4107,  1, tid);
    fwd_level(E3, A4, D4, 2061,  0, tid);

    // ---- median(|D1|): rank 4099 of 8199 ----
    // round 0: histogram was fused into fwd1
    hist_select(hist, 0u, 4099, 24, tid);
    __syncthreads();
    unsigned pref = (unsigned)hist[256];
    int kk = hist[257];
    __syncthreads();

    // round 1: byte1 histogram among top-byte matches
    for (int i = tid; i < 256; i += NT) hist[i] = 0;
    __syncthreads();
    for (int i = tid; i < 8199; i += NT) {
        unsigned b = __float_as_uint(fabsf(D1[i]));
        if ((b & 0xFF000000u) == pref) atomicAdd(&hist[(b >> 16) & 255], 1);
    }
    __syncthreads();
    hist_select(hist, pref, kk, 16, tid);
    __syncthreads();
    pref = (unsigned)hist[256];
    kk   = hist[257];
    if (tid == 0) hist[259] = 0;     // candidate counter
    __syncthreads();

    // compaction: gather elements matching the 16-bit prefix
    for (int i = tid; i < 8199; i += NT) {
        unsigned b = __float_as_uint(fabsf(D1[i]));
        if ((b >> 16) == (pref >> 16)) {
            int p = atomicAdd(&hist[259], 1);
            if (p < CAND_CAP) cand[p] = b;
        }
    }
    __syncthreads();
    const int ncand = hist[259];

    if (ncand <= CAND_CAP) {
        // single-warp exact rank select on the low 16 bits (no block barriers)
        if (tid < 32) {
            unsigned lowpref = 0;
            int kr = kk;
            for (int bit = 15; bit >= 0; bit--) {
                int c0 = 0;
                for (int i = tid; i < ncand; i += 32) {
                    unsigned lb = cand[i] & 0xFFFFu;
                    if ((lb >> (bit + 1)) == (lowpref >> (bit + 1)) && !((lb >> bit) & 1u))
                        c0++;
                }
                #pragma unroll
                for (int off = 16; off > 0; off >>= 1)
                    c0 += __shfl_xor_sync(0xFFFFFFFFu, c0, off);
                if (kr < c0) { /* bit = 0 */ }
                else { kr -= c0; lowpref |= 1u << bit; }
            }
            if (tid == 0) hist[256] = (int)(pref | lowpref);
        }
        __syncthreads();
        pref = (unsigned)hist[256];
    } else {
        // fallback: classic rounds 2 and 3
        for (int round = 2; round < 4; round++) {
            const int shift = 24 - 8 * round;
            const unsigned hmask = 0xFFFFFFFFu << (shift + 8);
            for (int i = tid; i < 256; i += NT) hist[i] = 0;
            __syncthreads();
            for (int i = tid; i < 8199; i += NT) {
                unsigned b = __float_as_uint(fabsf(D1[i]));
                if ((b & hmask) == pref) atomicAdd(&hist[(b >> shift) & 255], 1);
            }
            __syncthreads();
            hist_select(hist, pref, kk, shift, tid);
            __syncthreads();
            pref = (unsigned)hist[256];
            kk   = hist[257];
            __syncthreads();
        }
    }

    const float med = __uint_as_float(pref);
    const float thr = (med / 0.6745f) * 4.4054649f;   // sqrt(2*ln(16384))
    __syncthreads();   // cand region (== R3 slot) is rewritten below

    // inverse DWT with fused soft-thresholding, reusing dead regions
    inv_level(A4, D4, E3, 2061, thr, tid);
    inv_level(E3, D3, E2, 4107, thr, tid);
    inv_level(E2, D2, E1, 8199, thr, tid);
    inv_final(E1, D1, out + (size_t)row * 16384, thr, tid);
}

extern "C" void kernel_launch(void* const* d_in, const int* in_sizes, int n_in,
                              void* d_out, int out_size)
{
    const float* x = (const float*)d_in[0];
    float* out = (float*)d_out;
    const int rows = in_sizes[0] / 16384;   // 128*16 = 2048
    cudaFuncSetAttribute(wden_kernel, cudaFuncAttributeMaxDynamicSharedMemorySize, SMEM_BYTES);
    wden_kernel<<<rows, NT, SMEM_BYTES>>>(x, out, rows);
}

// round 13
// speedup vs baseline: 1.2124x; 1.2124x over previous
#include <cuda_runtime.h>

#define NT 512
typedef unsigned long long ull;

// ---- shared-memory layout (float offsets), aggressively aliased ----
// Region A [0, 8240): E1; after fwd2 dead: E3 at 0, D3 at 2112, A4 at 4192,
//   D4 at 5248; finally R1 (inv2 out) overwrites all of region A.
// Region B [8240, 16448): D1
// Region C [16448, 20608): E2 then R2
// Region D [20608, 24720): D2
// HIST [24720, 24980): dedicated (fused round-0 histogram during fwd1)
#define OFF_E1   0
#define OFF_E3   0
#define OFF_D3   2112
#define OFF_A4   4192
#define OFF_D4   5248
#define OFF_D1   8240
#define OFF_E2   16448
#define OFF_D2   20608
#define OFF_HIST 24720
#define SMEM_FLOATS (24720 + 260)
#define SMEM_BYTES  (SMEM_FLOATS * 4)

static constexpr float Hc[16] = {
    0.05441584224308161f,  0.3128715909144659f,   0.6756307362980128f,    0.5853546836548691f,
   -0.015829105256023893f,-0.2840155429624281f,   0.00047248457399797254f,0.128747426620186f,
   -0.01736930100202211f, -0.04408825393106472f,  0.013981027917015516f,  0.008746094047015655f,
   -0.00487035299301066f, -0.0003917403729959771f,0.0006754494059985568f,-0.00011747678400228192f };

__host__ __device__ static constexpr ull pk2(float lo, float hi) {
    return (ull)__builtin_bit_cast(unsigned int, lo) |
           ((ull)__builtin_bit_cast(unsigned int, hi) << 32);
}

#define DECL_FWD_COEF \
    const ull CA2[8] = { pk2(Hc[0],Hc[1]),  pk2(Hc[2],Hc[3]),  pk2(Hc[4],Hc[5]),  pk2(Hc[6],Hc[7]), \
                         pk2(Hc[8],Hc[9]),  pk2(Hc[10],Hc[11]),pk2(Hc[12],Hc[13]),pk2(Hc[14],Hc[15]) }; \
    const ull CD2[8] = { pk2(Hc[15],-Hc[14]),pk2(Hc[13],-Hc[12]),pk2(Hc[11],-Hc[10]),pk2(Hc[9],-Hc[8]), \
                         pk2(Hc[7],-Hc[6]),  pk2(Hc[5],-Hc[4]),  pk2(Hc[3],-Hc[2]),  pk2(Hc[1],-Hc[0]) }

#define DECL_INV_COEF \
    const ull CIA[8] = { pk2(Hc[14],Hc[15]), pk2(Hc[12],Hc[13]), pk2(Hc[10],Hc[11]), pk2(Hc[8],Hc[9]), \
                         pk2(Hc[6],Hc[7]),   pk2(Hc[4],Hc[5]),   pk2(Hc[2],Hc[3]),   pk2(Hc[0],Hc[1]) }; \
    const ull CIC[8] = { pk2(Hc[1],-Hc[0]),  pk2(Hc[3],-Hc[2]),  pk2(Hc[5],-Hc[4]),  pk2(Hc[7],-Hc[6]), \
                         pk2(Hc[9],-Hc[8]),  pk2(Hc[11],-Hc[10]),pk2(Hc[13],-Hc[12]),pk2(Hc[15],-Hc[14]) }

__device__ __forceinline__ void ff2(ull& a, ull v, ull c) {
    asm("fma.rn.f32x2 %0, %1, %2, %0;" : "+l"(a) : "l"(v), "l"(c));
}
__device__ __forceinline__ float hadd2(ull v) {
    float lo, hi;
    asm("mov.b64 {%0, %1}, %2;" : "=f"(lo), "=f"(hi) : "l"(v));
    return lo + hi;
}
__device__ __forceinline__ ull pkf(float lo, float hi) {
    ull r; asm("mov.b64 %0, {%1, %2};" : "=l"(r) : "f"(lo), "f"(hi)); return r;
}
__device__ __forceinline__ float2 upk2(ull v) {
    float2 r; asm("mov.b64 {%0, %1}, %2;" : "=f"(r.x), "=f"(r.y) : "l"(v)); return r;
}

__device__ __forceinline__ int symidx(int m) {
    if (m < 14)     return 13 - m;
    if (m > 16397)  return 32781 - m;
    return m - 14;
}

// Level-1 forward straight from gmem, packed-f32x2 taps, 2 outputs/thread-iter,
// conflict-free 16B lane stride. Fuses round-0 median histogram (hist is in a
// dedicated smem region — no alias with E1/D1).
__device__ void fwd1_gmem(const float* __restrict__ xr,
                          float* __restrict__ E1out,
                          float* __restrict__ D1,
                          int* __restrict__ hist, int tid)
{
    DECL_FWD_COEF;
    for (int v = tid; v < 4100; v += NT) {
        ull P[10];                          // P[p] = (e[2p], e[2p+1]), e[j]=E[4v-2+j]
        if (v >= 4 && v <= 4095) {
            const double2* px = (const double2*)(xr + 4 * v - 16);
            #pragma unroll
            for (int q = 0; q < 5; q++) {
                double2 t = px[q];
                P[2*q]   = __double_as_longlong(t.x);
                P[2*q+1] = __double_as_longlong(t.y);
            }
        } else {
            float e[20];
            e[0] = 0.f; e[1] = 0.f;
            #pragma unroll
            for (int j = 2; j < 20; j++) e[j] = xr[symidx(4 * v - 2 + j)];
            #pragma unroll
            for (int p = 0; p < 10; p++) P[p] = pkf(e[2*p], e[2*p+1]);
        }
        // w=2v uses P[1..8]; w=2v+1 uses P[2..9]
        ull a0 = 0, d0 = 0, a1 = 0, d1 = 0;
        #pragma unroll
        for (int m = 0; m < 8; m++) {
            ff2(a0, P[m+1], CA2[m]); ff2(d0, P[m+1], CD2[m]);
            ff2(a1, P[m+2], CA2[m]); ff2(d1, P[m+2], CD2[m]);
        }
        float ca0 = hadd2(a0), cd0 = hadd2(d0);
        float ca1 = hadd2(a1), cd1 = hadd2(d1);
        const int w0 = 2 * v;
        if (w0 + 2 <= 8199) {
            *(float2*)(E1out + 14 + w0) = make_float2(ca0, ca1);
            *(float2*)(D1 + w0)         = make_float2(cd0, cd1);
            atomicAdd(&hist[__float_as_uint(fabsf(cd0)) >> 24], 1);
            atomicAdd(&hist[__float_as_uint(fabsf(cd1)) >> 24], 1);
        } else if (w0 < 8199) {
            E1out[14 + w0] = ca0; D1[w0] = cd0;
            atomicAdd(&hist[__float_as_uint(fabsf(cd0)) >> 24], 1);
        }
    }
    __syncthreads();
    if (tid < 14)      E1out[tid] = E1out[27 - tid];
    else if (tid < 30) { int m = 8199 + tid; E1out[m] = E1out[16425 - m]; }
    __syncthreads();
}

// Forward DWT one level from an ext smem buffer, packed taps, 2 outputs/iter.
__device__ __forceinline__ void fwd_level(const float* __restrict__ Ein,
                                          float* __restrict__ caout,
                                          float* __restrict__ D,
                                          int L, int ext_out, int tid)
{
    DECL_FWD_COEF;
    const int Lc    = (L + 15) >> 1;
    const int npair = (Lc + 1) >> 1;
    const int caoff = ext_out ? 14 : 0;
    for (int u = tid; u < npair; u += NT) {
        const double2* p = (const double2*)(Ein + 4 * u);
        ull P[10];                          // P[m] = (E[4u+2m], E[4u+2m+1])
        #pragma unroll
        for (int q = 0; q < 5; q++) {
            double2 t = p[q];
            P[2*q]   = __double_as_longlong(t.x);
            P[2*q+1] = __double_as_longlong(t.y);
        }
        ull a0 = 0, d0 = 0, a1 = 0, d1 = 0;
        #pragma unroll
        for (int m = 0; m < 8; m++) {
            ff2(a0, P[m],   CA2[m]); ff2(d0, P[m],   CD2[m]);
            ff2(a1, P[m+1], CA2[m]); ff2(d1, P[m+1], CD2[m]);
        }
        float ca0 = hadd2(a0), cd0 = hadd2(d0);
        float ca1 = hadd2(a1), cd1 = hadd2(d1);
        const int w0 = 2 * u;
        if (w0 + 2 <= Lc) {
            *(float2*)(caout + caoff + w0) = make_float2(ca0, ca1);
            *(float2*)(D + w0)             = make_float2(cd0, cd1);
        } else if (w0 < Lc) {
            caout[caoff + w0] = ca0; D[w0] = cd0;
        }
    }
    __syncthreads();
    if (ext_out) {
        if (tid < 14)      caout[tid] = caout[27 - tid];
        else if (tid < 30) { int m = Lc + tid; caout[m] = caout[2 * Lc + 27 - m]; }
        __syncthreads();
    }
}

__device__ __forceinline__ float softthr(float v, float thr) {
    return copysignf(fmaxf(fabsf(v) - thr, 0.0f), v);
}

// Inverse DWT one level into smem; (re,ro) packed accumulator; fused threshold.
// Sparsity skip: after thresholding, ~99.99% of detail windows are all-zero,
// so test max|C| <= thr once and skip the entire C side (exact: softthr gives
// exactly 0 below thr).
__device__ __forceinline__ void inv_level(const float* __restrict__ ca,
                                          const float* __restrict__ cd,
                                          float* __restrict__ outsh,
                                          int n_out, float thr, int tid)
{
    DECL_INV_COEF;
    const int nu = (n_out + 7) >> 3;
    for (int u = tid; u < nu; u += NT) {
        const float4* pa = (const float4*)(ca + 4 * u);
        const float4* pc = (const float4*)(cd + 4 * u);
        float4 a0 = pa[0], a1 = pa[1], a2 = pa[2];
        float4 c0 = pc[0], c1 = pc[1], c2 = pc[2];
        float A[12] = { a0.x,a0.y,a0.z,a0.w, a1.x,a1.y,a1.z,a1.w, a2.x,a2.y,a2.z,a2.w };
        float C[12] = { c0.x,c0.y,c0.z,c0.w, c1.x,c1.y,c1.z,c1.w, c2.x,c2.y,c2.z,c2.w };
        ull Ad[12];
        #pragma unroll
        for (int m = 0; m < 12; m++) Ad[m] = pkf(A[m], A[m]);

        float mc = fabsf(C[0]);
        #pragma unroll
        for (int m = 1; m < 12; m++) mc = fmaxf(mc, fabsf(C[m]));

        float r[8];
        if (mc <= thr) {                    // common case: all details zeroed
            #pragma unroll
            for (int j = 0; j < 4; j++) {
                ull acc = 0;
                #pragma unroll
                for (int i = 0; i < 8; i++) ff2(acc, Ad[j+i], CIA[i]);
                float2 t = upk2(acc);
                r[2*j] = t.x; r[2*j+1] = t.y;
            }
        } else {
            ull Cd[12];
            #pragma unroll
            for (int m = 0; m < 12; m++) {
                float t = softthr(C[m], thr);
                Cd[m] = pkf(t, t);
            }
            #pragma unroll
            for (int j = 0; j < 4; j++) {
                ull acc = 0;
                #pragma unroll
                for (int i = 0; i < 8; i++) { ff2(acc, Ad[j+i], CIA[i]); ff2(acc, Cd[j+i], CIC[i]); }
                float2 t = upk2(acc);
                r[2*j] = t.x; r[2*j+1] = t.y;
            }
        }
        const int base = 8 * u;
        if (base + 8 <= n_out) {
            *(float4*)(outsh + base)     = make_float4(r[0], r[1], r[2], r[3]);
            *(float4*)(outsh + base + 4) = make_float4(r[4], r[5], r[6], r[7]);
        } else {
            #pragma unroll
            for (int j = 0; j < 8; j++)
                if (base + j < n_out) outsh[base + j] = r[j];
        }
    }
    __syncthreads();
}

// Final inverse level: n_out = 16384, writes straight to gmem. Same sparsity skip.
__device__ __forceinline__ void inv_final(const float* __restrict__ ca,
                                          const float* __restrict__ cd,
                                          float* __restrict__ gout, float thr, int tid)
{
    DECL_INV_COEF;
    for (int u = tid; u < 2048; u += NT) {
        const float4* pa = (const float4*)(ca + 4 * u);
        const float4* pc = (const float4*)(cd + 4 * u);
        float4 a0 = pa[0], a1 = pa[1], a2 = pa[2];
        float4 c0 = pc[0], c1 = pc[1], c2 = pc[2];
        float A[12] = { a0.x,a0.y,a0.z,a0.w, a1.x,a1.y,a1.z,a1.w, a2.x,a2.y,a2.z,a2.w };
        float C[12] = { c0.x,c0.y,c0.z,c0.w, c1.x,c1.y,c1.z,c1.w, c2.x,c2.y,c2.z,c2.w };
        ull Ad[12];
        #pragma unroll
        for (int m = 0; m < 12; m++) Ad[m] = pkf(A[m], A[m]);

        float mc = fabsf(C[0]);
        #pragma unroll
        for (int m = 1; m < 12; m++) mc = fmaxf(mc, fabsf(C[m]));

        float r[8];
        if (mc <= thr) {
            #pragma unroll
            for (int j = 0; j < 4; j++) {
                ull acc = 0;
                #pragma unroll
                for (int i = 0; i < 8; i++) ff2(acc, Ad[j+i], CIA[i]);
                float2 t = upk2(acc);
                r[2*j] = t.x; r[2*j+1] = t.y;
            }
        } else {
            ull Cd[12];
            #pragma unroll
            for (int m = 0; m < 12; m++) {
                float t = softthr(C[m], thr);
                Cd[m] = pkf(t, t);
            }
            #pragma unroll
            for (int j = 0; j < 4; j++) {
                ull acc = 0;
                #pragma unroll
                for (int i = 0; i < 8; i++) { ff2(acc, Ad[j+i], CIA[i]); ff2(acc, Cd[j+i], CIC[i]); }
                float2 t = upk2(acc);
                r[2*j] = t.x; r[2*j+1] = t.y;
            }
        }
        float4* po = (float4*)(gout + 8 * u);
        po[0] = make_float4(r[0], r[1], r[2], r[3]);
        po[1] = make_float4(r[4], r[5], r[6], r[7]);
    }
}

__global__ void __launch_bounds__(NT, 2)
wden_kernel(const float* __restrict__ x, float* __restrict__ out, int rows)
{
    extern __shared__ float sm[];
    const int tid = threadIdx.x;
    const int row = blockIdx.x;
    if (row >= rows) return;

    float* E1 = sm + OFF_E1;
    float* E3 = sm + OFF_E3;
    float* D3 = sm + OFF_D3;
    float* A4 = sm + OFF_A4;
    float* D4 = sm + OFF_D4;
    float* D1 = sm + OFF_D1;
    float* E2 = sm + OFF_E2;
    float* D2 = sm + OFF_D2;
    int*   hist = (int*)(sm + OFF_HIST);

    const float* xr = x + (size_t)row * 16384;

    // zero histogram for the fused round-0 median pass
    for (int i = tid; i < 256; i += NT) hist[i] = 0;
    __syncthreads();

    // forward DWT: 16384 -> 8199 -> 4107 -> 2061 -> 1038
    fwd1_gmem(xr, E1, D1, hist, tid);           // also fills round-0 histogram
    fwd_level(E1, E2, D2, 8199,  1, tid);
    fwd_level(E2, E3, D3, 4107,  1, tid);
    fwd_level(E3, A4, D4, 2061,  0, tid);

    // median(|D1|): rank 4099 of 8199, 4-round MSB radix select on float bits.
    // Round 0 histogram was fused into fwd1_gmem.
    unsigned pref = 0; int kk = 4099;
    for (int round = 0; round < 4; round++) {
        const int shift = 24 - 8 * round;
        if (round > 0) {
            const unsigned hmask = 0xFFFFFFFFu << (shift + 8);
            for (int i = tid; i < 256; i += NT) hist[i] = 0;
            __syncthreads();
            for (int i = tid; i < 8199; i += NT) {
                unsigned b = __float_as_uint(fabsf(D1[i]));
                if ((b & hmask) == pref) atomicAdd(&hist[(b >> shift) & 255], 1);
            }
            __syncthreads();
        }
        if (tid < 32) {
            int s[8]; int tot = 0;
            #pragma unroll
            for (int j = 0; j < 8; j++) { s[j] = hist[tid * 8 + j]; tot += s[j]; }
            int run = tot;
            #pragma unroll
            for (int off = 1; off < 32; off <<= 1) {
                int n = __shfl_up_sync(0xFFFFFFFFu, run, off);
                if (tid >= (unsigned)off) run += n;
            }
            int excl = run - tot;
            if (kk >= excl && kk < excl + tot) {
                int acc = excl;
                #pragma unroll
                for (int j = 0; j < 8; j++) {
                    if (acc + s[j] > kk) {
                        hist[256] = (int)(pref | ((unsigned)(tid * 8 + j) << shift));
                        hist[257] = kk - acc;
                        break;
                    }
                    acc += s[j];
                }
            }
        }
        __syncthreads();
        pref = (unsigned)hist[256];
        kk   = hist[257];
    }
    const float med = __uint_as_float(pref);
    const float thr = (med / 0.6745f) * 4.4054649f;   // sqrt(2*ln(16384))

    // inverse DWT with fused soft-thresholding + sparsity skip
    inv_level(A4, D4, E3, 2061, thr, tid);
    inv_level(E3, D3, E2, 4107, thr, tid);
    inv_level(E2, D2, E1, 8199, thr, tid);
    inv_final(E1, D1, out + (size_t)row * 16384, thr, tid);
}

extern "C" void kernel_launch(void* const* d_in, const int* in_sizes, int n_in,
                              void* d_out, int out_size)
{
    const float* x = (const float*)d_in[0];
    float* out = (float*)d_out;
    const int rows = in_sizes[0] / 16384;   // 128*16 = 2048
    cudaFuncSetAttribute(wden_kernel, cudaFuncAttributeMaxDynamicSharedMemorySize, SMEM_BYTES);
    wden_kernel<<<rows, NT, SMEM_BYTES>>>(x, out, rows);
}